// round 11
// baseline (speedup 1.0000x reference)
#include <cuda_runtime.h>
#include <cuda_bf16.h>
#include <cuda_fp16.h>

// Problem constants (fixed by setup_inputs)
constexpr int NN = 100000;   // nodes
constexpr int EE = 1600000;  // edges
// layer1: in=128, H=4, D=32 (H*D=128); layer2: in=32, H=1, D=16

constexpr int SCAN_BLK = 1024;
constexpr int NBLK = (NN + SCAN_BLK - 1) / SCAN_BLK;   // 98

// ---------------- scratch (__device__ globals; no allocation allowed) -------
// g_deg relies on zero-init at module load; scan_final re-zeroes it each call
// after consuming it (self-cleaning invariant, graph-replay safe).
__device__ __half g_feat1h[(size_t)NN * 128]; // x @ W1 as fp16 (25.6 MB)
__device__ float g_el1[NN * 4];
__device__ float g_er1[NN * 4];
__device__ int   g_deg[NN];
__device__ int   g_rowptr[NN + 1];
__device__ int   g_pos[NN];
__device__ int   g_esrc[EE];                // CSR: src per dst-sorted edge
__device__ int   g_blocksum[NBLK];
__device__ float g_h2[(size_t)NN * 32];     // relu(mean over heads)
__device__ float g_feat2[(size_t)NN * 16];  // h2 @ W2
__device__ float g_el2[NN];
__device__ float g_er2[NN];

// ---------------- helpers ----------------------------------------------------
__device__ __forceinline__ float ftf32(float x) {
    float y;
    asm("cvt.rna.tf32.f32 %0, %1;" : "=f"(y) : "f"(x));
    return y;
}

__device__ __forceinline__ void mma_tf32(float c[4], const unsigned a[4], const unsigned b[2]) {
    asm volatile(
        "mma.sync.aligned.m16n8k8.row.col.f32.tf32.tf32.f32 "
        "{%0,%1,%2,%3}, {%4,%5,%6,%7}, {%8,%9}, {%0,%1,%2,%3};"
        : "+f"(c[0]), "+f"(c[1]), "+f"(c[2]), "+f"(c[3])
        : "r"(a[0]), "r"(a[1]), "r"(a[2]), "r"(a[3]), "r"(b[0]), "r"(b[1]));
}

// ---------------- K: GEMM1 (tf32 tensor cores) + fused el/er epilogue --------
constexpr int WT_STRIDE = 132;
constexpr int AS_STRIDE = 36;
constexpr int SMEM_WT_FLOATS = 128 * WT_STRIDE;          // 16896
constexpr int SMEM_AS_FLOATS = 2 * 128 * AS_STRIDE;      // 9216
constexpr int GEMM_SMEM_BYTES = (SMEM_WT_FLOATS + SMEM_AS_FLOATS) * 4;  // 104448

__global__ __launch_bounds__(256) void gemm1_kernel(
    const float* __restrict__ x, const float* __restrict__ W,
    const float* __restrict__ al, const float* __restrict__ ar) {
    extern __shared__ float smem[];
    float* Wt = smem;                       // [128][132]
    float* As = smem + SMEM_WT_FLOATS;      // [2][128][36]
    float* cbuf = smem;                     // reuse after mainloop: [128][132]

    int tid = threadIdx.x;
    int lane = tid & 31;
    int warp = tid >> 5;
    int blockM = blockIdx.x * 128;
    int mrow = (warp & 3) * 32;
    int ncol = (warp >> 2) * 64;

    // Load + transpose + tf32-convert W -> Wt[n][k]
#pragma unroll
    for (int i = 0; i < 16; i++) {
        int f = tid + i * 256;            // float4 index, 0..4095
        int k = f >> 5;
        int n4 = (f & 31) * 4;
        float4 v = *(const float4*)&W[(size_t)k * 128 + n4];
        Wt[(n4 + 0) * WT_STRIDE + k] = ftf32(v.x);
        Wt[(n4 + 1) * WT_STRIDE + k] = ftf32(v.y);
        Wt[(n4 + 2) * WT_STRIDE + k] = ftf32(v.z);
        Wt[(n4 + 3) * WT_STRIDE + k] = ftf32(v.w);
    }

    // A slab loader: 128 rows x 32 k
    auto load_slab = [&](int slab, int buf) {
        int row = tid >> 1;
        int base = (tid & 1) * 16;
        int gr = blockM + row;
        if (gr >= NN) gr = NN - 1;  // clamp: garbage rows discarded at store
        const float4* xp = (const float4*)&x[(size_t)gr * 128 + slab * 32 + base];
        float* dstp = &As[buf * 128 * AS_STRIDE + row * AS_STRIDE + base];
#pragma unroll
        for (int q = 0; q < 4; q++) {
            float4 v = xp[q];
            dstp[q * 4 + 0] = ftf32(v.x);
            dstp[q * 4 + 1] = ftf32(v.y);
            dstp[q * 4 + 2] = ftf32(v.z);
            dstp[q * 4 + 3] = ftf32(v.w);
        }
    };

    load_slab(0, 0);
    __syncthreads();

    float acc[2][8][4];
#pragma unroll
    for (int mt = 0; mt < 2; mt++)
#pragma unroll
        for (int nt = 0; nt < 8; nt++)
#pragma unroll
            for (int q = 0; q < 4; q++) acc[mt][nt][q] = 0.f;

    int r4 = lane >> 2;   // 0..7
    int c4 = lane & 3;    // 0..3

    int buf = 0;
    for (int slab = 0; slab < 4; slab++) {
        if (slab < 3) load_slab(slab + 1, buf ^ 1);
        const float* Ab = &As[buf * 128 * AS_STRIDE];
#pragma unroll
        for (int ks = 0; ks < 4; ks++) {
            int kg = slab * 32 + ks * 8;
            unsigned b[8][2];
#pragma unroll
            for (int nt = 0; nt < 8; nt++) {
                int n = ncol + nt * 8 + r4;
                b[nt][0] = __float_as_uint(Wt[n * WT_STRIDE + kg + c4]);
                b[nt][1] = __float_as_uint(Wt[n * WT_STRIDE + kg + c4 + 4]);
            }
            unsigned a[2][4];
#pragma unroll
            for (int mt = 0; mt < 2; mt++) {
                int r = mrow + mt * 16 + r4;
                int kk = ks * 8 + c4;
                a[mt][0] = __float_as_uint(Ab[r * AS_STRIDE + kk]);
                a[mt][1] = __float_as_uint(Ab[(r + 8) * AS_STRIDE + kk]);
                a[mt][2] = __float_as_uint(Ab[r * AS_STRIDE + kk + 4]);
                a[mt][3] = __float_as_uint(Ab[(r + 8) * AS_STRIDE + kk + 4]);
            }
#pragma unroll
            for (int mt = 0; mt < 2; mt++)
#pragma unroll
                for (int nt = 0; nt < 8; nt++) mma_tf32(acc[mt][nt], a[mt], b[nt]);
        }
        __syncthreads();
        buf ^= 1;
    }

    // Stage accumulators to smem (cbuf[row][col], stride 132)
#pragma unroll
    for (int mt = 0; mt < 2; mt++)
#pragma unroll
        for (int nt = 0; nt < 8; nt++) {
            int r = mrow + mt * 16 + r4;
            int c = ncol + nt * 8 + 2 * c4;
            *(float2*)&cbuf[r * WT_STRIDE + c] = make_float2(acc[mt][nt][0], acc[mt][nt][1]);
            *(float2*)&cbuf[(r + 8) * WT_STRIDE + c] = make_float2(acc[mt][nt][2], acc[mt][nt][3]);
        }
    __syncthreads();

    // Epilogue: coalesced fp16 store + fused el/er head-dots.
    {
        int row = tid >> 1;
        int half = tid & 1;
        int grow = blockM + row;
        if (grow < NN) {
            const float* crow = &cbuf[row * WT_STRIDE + half * 64];
            int cbase = half * 64;
            float elh[2] = {0.f, 0.f}, erh[2] = {0.f, 0.f};
            __half2 hb[32];
#pragma unroll
            for (int j = 0; j < 64; j += 2) {
                float v0 = crow[j], v1 = crow[j + 1];
                int hh = j >> 5;
                elh[hh] += v0 * __ldg(&al[cbase + j]) + v1 * __ldg(&al[cbase + j + 1]);
                erh[hh] += v0 * __ldg(&ar[cbase + j]) + v1 * __ldg(&ar[cbase + j + 1]);
                hb[j >> 1] = __floats2half2_rn(v0, v1);
            }
            uint4* dsth = (uint4*)(g_feat1h + (size_t)grow * 128 + cbase);
            const uint4* srch = (const uint4*)hb;
#pragma unroll
            for (int q = 0; q < 8; q++) dsth[q] = srch[q];
            int hbase = half * 2;
            g_el1[grow * 4 + hbase + 0] = elh[0];
            g_el1[grow * 4 + hbase + 1] = elh[1];
            g_er1[grow * 4 + hbase + 0] = erh[0];
            g_er1[grow * 4 + hbase + 1] = erh[1];
        }
    }
}

// ---------------- K: degree histogram (scalar: max atomic MLP) ---------------
__global__ void hist_kernel(const int* __restrict__ dst) {
    int i = blockIdx.x * blockDim.x + threadIdx.x;
    if (i < EE) atomicAdd(&g_deg[dst[i]], 1);
}

// ---------------- hierarchical scan ------------------------------------------
// K1: per-block sums of g_deg (1024 elems per block)
__global__ __launch_bounds__(SCAN_BLK) void blocksum_kernel() {
    __shared__ int wsum[32];
    int i = blockIdx.x * SCAN_BLK + threadIdx.x;
    int v = (i < NN) ? g_deg[i] : 0;
#pragma unroll
    for (int off = 16; off > 0; off >>= 1) v += __shfl_xor_sync(0xffffffffu, v, off);
    int lane = threadIdx.x & 31, wid = threadIdx.x >> 5;
    if (lane == 0) wsum[wid] = v;
    __syncthreads();
    if (wid == 0) {
        int s = wsum[lane];
#pragma unroll
        for (int off = 16; off > 0; off >>= 1) s += __shfl_xor_sync(0xffffffffu, s, off);
        if (lane == 0) g_blocksum[blockIdx.x] = s;
    }
}

// K2: block-local exclusive scan + (inlined) block offset -> rowptr/pos.
// Self-cleaning: zeroes g_deg after reading (restores invariant for next call).
__global__ __launch_bounds__(SCAN_BLK) void scan_final_kernel() {
    __shared__ int wsum[32];
    __shared__ int s_boff;
    int t = threadIdx.x;
    int lane = t & 31, wid = t >> 5;

    // block offset: sum of blocksums with index < blockIdx.x (redundant per block)
    {
        int v = (t < NBLK && t < (int)blockIdx.x) ? g_blocksum[t] : 0;
#pragma unroll
        for (int off = 16; off > 0; off >>= 1) v += __shfl_xor_sync(0xffffffffu, v, off);
        if (lane == 0) wsum[wid] = v;
        __syncthreads();
        if (t == 0) {
            int s = 0;
#pragma unroll
            for (int k = 0; k < 32; k++) s += wsum[k];
            s_boff = s;
        }
        __syncthreads();
    }

    int i = blockIdx.x * SCAN_BLK + t;
    int d = (i < NN) ? g_deg[i] : 0;
    int inc = d;
#pragma unroll
    for (int off = 1; off < 32; off <<= 1) {
        int u = __shfl_up_sync(0xffffffffu, inc, off);
        if (lane >= off) inc += u;
    }
    __syncthreads();   // wsum reuse guard (s_boff consumed)
    if (lane == 31) wsum[wid] = inc;
    __syncthreads();
    if (wid == 0) {
        int s = wsum[lane];
        int sinc = s;
#pragma unroll
        for (int off = 1; off < 32; off <<= 1) {
            int u = __shfl_up_sync(0xffffffffu, sinc, off);
            if (lane >= off) sinc += u;
        }
        wsum[lane] = sinc - s;   // exclusive warp prefix
    }
    __syncthreads();
    if (i < NN) {
        int off = s_boff + wsum[wid] + inc - d;
        g_rowptr[i] = off;
        g_pos[i] = off;
        g_deg[i] = 0;            // self-clean for next graph replay
    }
    if (blockIdx.x == 0 && t == 0) g_rowptr[NN] = EE;
}

// ---------------- K: scatter edges into CSR (scalar: max atomic MLP) ---------
__global__ void scatter_kernel(const int* __restrict__ src, const int* __restrict__ dst) {
    int i = blockIdx.x * blockDim.x + threadIdx.x;
    if (i < EE) {
        int p = atomicAdd(&g_pos[dst[i]], 1);
        g_esrc[p] = src[i];
    }
}

// ---------------- K: layer1 aggregation (fused softmax) + mean-head + relu --
// one warp per dst node, 2 edges per iteration, SOFTWARE-PIPELINED gathers:
//   half = lane>>4 selects edge p+half; sub = lane&15 owns dims 8*sub..8*sub+7
//   head h = sub>>2. Next iteration's esrc/el1/feat loads issue before the
//   current iteration's FMA chain, hiding the serial L2 round-trips.
__global__ void agg1_kernel(const float* __restrict__ b1) {
    int w = (blockIdx.x * blockDim.x + threadIdx.x) >> 5;
    if (w >= NN) return;
    int lane = threadIdx.x & 31;
    int half = lane >> 4;
    int sub = lane & 15;
    int h = sub >> 2;
    float ern = g_er1[w * 4 + h];
    float acc[8];
#pragma unroll
    for (int q = 0; q < 8; q++) acc[q] = 0.f;
    float den = 0.f;
    int p0 = g_rowptr[w], p1 = g_rowptr[w + 1];

    if (p0 < p1) {
        // prologue: stage edge p0+half (clamped)
        int idx = p0 + half;
        int s = g_esrc[idx < p1 ? idx : p1 - 1];
        float el = g_el1[s * 4 + h];
        uint4 u = *(const uint4*)(g_feat1h + ((size_t)s << 7) + (sub << 3));

        for (int p = p0; p < p1; p += 2) {
            // prefetch next pair while current computes
            int pn = p + 2;
            int s2 = s; float el2 = 0.f; uint4 u2 = u;
            if (pn < p1) {
                int nidx = pn + half;
                s2 = g_esrc[nidx < p1 ? nidx : p1 - 1];
                el2 = g_el1[s2 * 4 + h];
                u2 = *(const uint4*)(g_feat1h + ((size_t)s2 << 7) + (sub << 3));
            }
            bool valid = (p + half) < p1;
            float e = el + ern;
            e = fmaxf(e, 0.2f * e);                   // leaky relu
            float ex = valid ? __expf(e) : 0.f;
            const __half2* hp = (const __half2*)&u;
#pragma unroll
            for (int q = 0; q < 4; q++) {
                float2 f = __half22float2(hp[q]);
                acc[2 * q]     += ex * f.x;
                acc[2 * q + 1] += ex * f.y;
            }
            den += ex;
            s = s2; el = el2; u = u2;
        }
    }

    // merge the two edge-halves (same node, disjoint edge subsets)
#pragma unroll
    for (int q = 0; q < 8; q++) acc[q] += __shfl_xor_sync(0xffffffffu, acc[q], 16);
    den += __shfl_xor_sync(0xffffffffu, den, 16);
    float inv = den > 0.f ? 1.f / den : 0.f;
    float v[8];
    float4 b0 = *(const float4*)&b1[sub * 8];
    float4 b1v = *(const float4*)&b1[sub * 8 + 4];
    v[0] = acc[0] * inv + b0.x;  v[1] = acc[1] * inv + b0.y;
    v[2] = acc[2] * inv + b0.z;  v[3] = acc[3] * inv + b0.w;
    v[4] = acc[4] * inv + b1v.x; v[5] = acc[5] * inv + b1v.y;
    v[6] = acc[6] * inv + b1v.z; v[7] = acc[7] * inv + b1v.w;
    // sum over the 4 heads: head = sub>>2 -> xor sub bits 2 (4) and 3 (8)
#pragma unroll
    for (int q = 0; q < 8; q++) {
        v[q] += __shfl_xor_sync(0xffffffffu, v[q], 4);
        v[q] += __shfl_xor_sync(0xffffffffu, v[q], 8);
    }
    if (lane < 4) {   // sub 0..3, half 0: dims d = lane*8 + q
        float4 o0 = make_float4(fmaxf(v[0] * 0.25f, 0.f), fmaxf(v[1] * 0.25f, 0.f),
                                fmaxf(v[2] * 0.25f, 0.f), fmaxf(v[3] * 0.25f, 0.f));
        float4 o1 = make_float4(fmaxf(v[4] * 0.25f, 0.f), fmaxf(v[5] * 0.25f, 0.f),
                                fmaxf(v[6] * 0.25f, 0.f), fmaxf(v[7] * 0.25f, 0.f));
        *(float4*)&g_h2[(size_t)w * 32 + lane * 8] = o0;
        *(float4*)&g_h2[(size_t)w * 32 + lane * 8 + 4] = o1;
    }
}

// ---------------- K: feat2 = h2 @ W2; el2/er2 --------------------------------
__global__ void feat2_kernel(const float* __restrict__ W2,
                             const float* __restrict__ al2,
                             const float* __restrict__ ar2) {
    int n = blockIdx.x * blockDim.x + threadIdx.x;
    if (n >= NN) return;
    float hrow[32];
#pragma unroll
    for (int i = 0; i < 8; i++)
        *(float4*)&hrow[i * 4] = *(const float4*)&g_h2[(size_t)n * 32 + i * 4];
    float out[16];
#pragma unroll
    for (int d = 0; d < 16; d++) out[d] = 0.f;
#pragma unroll
    for (int k = 0; k < 32; k++) {
        float hv = hrow[k];
#pragma unroll
        for (int d = 0; d < 16; d++) out[d] += hv * __ldg(&W2[k * 16 + d]);
    }
    float el = 0.f, er = 0.f;
#pragma unroll
    for (int d = 0; d < 16; d++) {
        el += out[d] * __ldg(&al2[d]);
        er += out[d] * __ldg(&ar2[d]);
    }
#pragma unroll
    for (int i = 0; i < 4; i++)
        *(float4*)&g_feat2[(size_t)n * 16 + i * 4] =
            make_float4(out[i*4+0], out[i*4+1], out[i*4+2], out[i*4+3]);
    g_el2[n] = el;
    g_er2[n] = er;
}

// ---------------- K: layer2 aggregation (fused softmax, pipelined) -----------
__global__ void agg2_kernel(const float* __restrict__ b2, float* __restrict__ out) {
    int g = (blockIdx.x * blockDim.x + threadIdx.x) >> 4;
    if (g >= NN) return;
    int lane = threadIdx.x & 15;
    float ern = g_er2[g];
    float acc = 0.f, den = 0.f;
    int p0 = g_rowptr[g], p1 = g_rowptr[g + 1];
    if (p0 < p1) {
        int s = g_esrc[p0];
        float el = g_el2[s];
        float f = g_feat2[(size_t)s * 16 + lane];
        for (int p = p0; p < p1; p++) {
            int s2 = s; float el2 = el, f2 = f;
            if (p + 1 < p1) {
                s2 = g_esrc[p + 1];
                el2 = g_el2[s2];
                f2 = g_feat2[(size_t)s2 * 16 + lane];
            }
            float e = el + ern;
            e = fmaxf(e, 0.2f * e);
            float ex = __expf(e);
            acc += ex * f;
            den += ex;
            s = s2; el = el2; f = f2;
        }
    }
    float inv = den > 0.f ? 1.f / den : 0.f;
    out[(size_t)g * 16 + lane] = acc * inv + b2[lane];
}

// ---------------- launch ------------------------------------------------------
// Fork/join stream overlap: gemm1 (tensor/smem-bound) on a side stream runs
// concurrently with the CSR build chain (atomic/L2-bound) on the main stream.
extern "C" void kernel_launch(void* const* d_in, const int* in_sizes, int n_in,
                              void* d_out, int out_size) {
    const float* x   = (const float*)d_in[0];
    const int*   src = (const int*)d_in[1];
    const int*   dst = (const int*)d_in[2];
    const float* W1  = (const float*)d_in[3];
    const float* al1 = (const float*)d_in[4];
    const float* ar1 = (const float*)d_in[5];
    const float* b1  = (const float*)d_in[6];
    const float* W2  = (const float*)d_in[7];
    const float* al2 = (const float*)d_in[8];
    const float* ar2 = (const float*)d_in[9];
    const float* b2  = (const float*)d_in[10];
    float* out = (float*)d_out;

    (void)in_sizes; (void)n_in; (void)out_size;

    static cudaStream_t s_side = nullptr;
    static cudaEvent_t s_fork = nullptr, s_join = nullptr;
    if (s_side == nullptr) {
        cudaStreamCreateWithFlags(&s_side, cudaStreamNonBlocking);
        cudaEventCreateWithFlags(&s_fork, cudaEventDisableTiming);
        cudaEventCreateWithFlags(&s_join, cudaEventDisableTiming);
        cudaFuncSetAttribute(gemm1_kernel, cudaFuncAttributeMaxDynamicSharedMemorySize,
                             GEMM_SMEM_BYTES);
    }

    // fork: side stream = gemm1 (independent of the CSR chain)
    cudaEventRecord(s_fork, 0);
    cudaStreamWaitEvent(s_side, s_fork, 0);
    gemm1_kernel<<<(NN + 127) / 128, 256, GEMM_SMEM_BYTES, s_side>>>(x, W1, al1, ar1);
    cudaEventRecord(s_join, s_side);

    // main stream: CSR build chain (g_deg zeroed by previous call's scan_final)
    hist_kernel<<<(EE + 255) / 256, 256>>>(dst);
    blocksum_kernel<<<NBLK, SCAN_BLK>>>();
    scan_final_kernel<<<NBLK, SCAN_BLK>>>();
    scatter_kernel<<<(EE + 255) / 256, 256>>>(src, dst);

    // join: agg1 needs both gemm1 outputs and the CSR
    cudaStreamWaitEvent(0, s_join, 0);
    agg1_kernel<<<(NN * 32 + 255) / 256, 256>>>(b1);
    feat2_kernel<<<(NN + 255) / 256, 256>>>(W2, al2, ar2);
    agg2_kernel<<<(NN * 16 + 255) / 256, 256>>>(b2, out);
}

// round 12
// speedup vs baseline: 1.6039x; 1.6039x over previous
#include <cuda_runtime.h>
#include <cuda_bf16.h>
#include <cuda_fp16.h>

// Problem constants (fixed by setup_inputs)
constexpr int NN = 100000;   // nodes
constexpr int EE = 1600000;  // edges
// layer1: in=128, H=4, D=32 (H*D=128); layer2: in=32, H=1, D=16

constexpr int SCAN_BLK = 1024;
constexpr int NBLK = (NN + SCAN_BLK - 1) / SCAN_BLK;   // 98

// ---------------- scratch (__device__ globals; no allocation allowed) -------
// g_deg relies on zero-init at module load; scan_final re-zeroes it each call
// after consuming it (self-cleaning invariant, graph-replay safe).
__device__ __half g_feat1h[(size_t)NN * 128]; // x @ W1 as fp16 (25.6 MB)
__device__ float g_el1[NN * 4];
__device__ float g_er1[NN * 4];
__device__ int   g_deg[NN];
__device__ int   g_rowptr[NN + 1];
__device__ int   g_pos[NN];
__device__ int   g_esrc[EE];                // CSR: src per dst-sorted edge
__device__ int   g_blocksum[NBLK];
__device__ float g_h2[(size_t)NN * 32];     // relu(mean over heads)
__device__ float g_feat2[(size_t)NN * 16];  // h2 @ W2
__device__ float g_el2[NN];
__device__ float g_er2[NN];

// ---------------- helpers ----------------------------------------------------
__device__ __forceinline__ float ftf32(float x) {
    float y;
    asm("cvt.rna.tf32.f32 %0, %1;" : "=f"(y) : "f"(x));
    return y;
}

__device__ __forceinline__ void mma_tf32(float c[4], const unsigned a[4], const unsigned b[2]) {
    asm volatile(
        "mma.sync.aligned.m16n8k8.row.col.f32.tf32.tf32.f32 "
        "{%0,%1,%2,%3}, {%4,%5,%6,%7}, {%8,%9}, {%0,%1,%2,%3};"
        : "+f"(c[0]), "+f"(c[1]), "+f"(c[2]), "+f"(c[3])
        : "r"(a[0]), "r"(a[1]), "r"(a[2]), "r"(a[3]), "r"(b[0]), "r"(b[1]));
}

// ---------------- K: GEMM1 (tf32 tensor cores) + fused el/er epilogue --------
constexpr int WT_STRIDE = 132;
constexpr int AS_STRIDE = 36;
constexpr int SMEM_WT_FLOATS = 128 * WT_STRIDE;          // 16896
constexpr int SMEM_AS_FLOATS = 2 * 128 * AS_STRIDE;      // 9216
constexpr int GEMM_SMEM_BYTES = (SMEM_WT_FLOATS + SMEM_AS_FLOATS) * 4;  // 104448

__global__ __launch_bounds__(256) void gemm1_kernel(
    const float* __restrict__ x, const float* __restrict__ W,
    const float* __restrict__ al, const float* __restrict__ ar) {
    extern __shared__ float smem[];
    float* Wt = smem;                       // [128][132]
    float* As = smem + SMEM_WT_FLOATS;      // [2][128][36]
    float* cbuf = smem;                     // reuse after mainloop: [128][132]

    int tid = threadIdx.x;
    int lane = tid & 31;
    int warp = tid >> 5;
    int blockM = blockIdx.x * 128;
    int mrow = (warp & 3) * 32;
    int ncol = (warp >> 2) * 64;

    // Load + transpose + tf32-convert W -> Wt[n][k]
#pragma unroll
    for (int i = 0; i < 16; i++) {
        int f = tid + i * 256;            // float4 index, 0..4095
        int k = f >> 5;
        int n4 = (f & 31) * 4;
        float4 v = *(const float4*)&W[(size_t)k * 128 + n4];
        Wt[(n4 + 0) * WT_STRIDE + k] = ftf32(v.x);
        Wt[(n4 + 1) * WT_STRIDE + k] = ftf32(v.y);
        Wt[(n4 + 2) * WT_STRIDE + k] = ftf32(v.z);
        Wt[(n4 + 3) * WT_STRIDE + k] = ftf32(v.w);
    }

    // A slab loader: 128 rows x 32 k
    auto load_slab = [&](int slab, int buf) {
        int row = tid >> 1;
        int base = (tid & 1) * 16;
        int gr = blockM + row;
        if (gr >= NN) gr = NN - 1;  // clamp: garbage rows discarded at store
        const float4* xp = (const float4*)&x[(size_t)gr * 128 + slab * 32 + base];
        float* dstp = &As[buf * 128 * AS_STRIDE + row * AS_STRIDE + base];
#pragma unroll
        for (int q = 0; q < 4; q++) {
            float4 v = xp[q];
            dstp[q * 4 + 0] = ftf32(v.x);
            dstp[q * 4 + 1] = ftf32(v.y);
            dstp[q * 4 + 2] = ftf32(v.z);
            dstp[q * 4 + 3] = ftf32(v.w);
        }
    };

    load_slab(0, 0);
    __syncthreads();

    float acc[2][8][4];
#pragma unroll
    for (int mt = 0; mt < 2; mt++)
#pragma unroll
        for (int nt = 0; nt < 8; nt++)
#pragma unroll
            for (int q = 0; q < 4; q++) acc[mt][nt][q] = 0.f;

    int r4 = lane >> 2;   // 0..7
    int c4 = lane & 3;    // 0..3

    int buf = 0;
    for (int slab = 0; slab < 4; slab++) {
        if (slab < 3) load_slab(slab + 1, buf ^ 1);
        const float* Ab = &As[buf * 128 * AS_STRIDE];
#pragma unroll
        for (int ks = 0; ks < 4; ks++) {
            int kg = slab * 32 + ks * 8;
            unsigned b[8][2];
#pragma unroll
            for (int nt = 0; nt < 8; nt++) {
                int n = ncol + nt * 8 + r4;
                b[nt][0] = __float_as_uint(Wt[n * WT_STRIDE + kg + c4]);
                b[nt][1] = __float_as_uint(Wt[n * WT_STRIDE + kg + c4 + 4]);
            }
            unsigned a[2][4];
#pragma unroll
            for (int mt = 0; mt < 2; mt++) {
                int r = mrow + mt * 16 + r4;
                int kk = ks * 8 + c4;
                a[mt][0] = __float_as_uint(Ab[r * AS_STRIDE + kk]);
                a[mt][1] = __float_as_uint(Ab[(r + 8) * AS_STRIDE + kk]);
                a[mt][2] = __float_as_uint(Ab[r * AS_STRIDE + kk + 4]);
                a[mt][3] = __float_as_uint(Ab[(r + 8) * AS_STRIDE + kk + 4]);
            }
#pragma unroll
            for (int mt = 0; mt < 2; mt++)
#pragma unroll
                for (int nt = 0; nt < 8; nt++) mma_tf32(acc[mt][nt], a[mt], b[nt]);
        }
        __syncthreads();
        buf ^= 1;
    }

    // Stage accumulators to smem (cbuf[row][col], stride 132)
#pragma unroll
    for (int mt = 0; mt < 2; mt++)
#pragma unroll
        for (int nt = 0; nt < 8; nt++) {
            int r = mrow + mt * 16 + r4;
            int c = ncol + nt * 8 + 2 * c4;
            *(float2*)&cbuf[r * WT_STRIDE + c] = make_float2(acc[mt][nt][0], acc[mt][nt][1]);
            *(float2*)&cbuf[(r + 8) * WT_STRIDE + c] = make_float2(acc[mt][nt][2], acc[mt][nt][3]);
        }
    __syncthreads();

    // Epilogue: coalesced fp16 store + fused el/er head-dots.
    {
        int row = tid >> 1;
        int half = tid & 1;
        int grow = blockM + row;
        if (grow < NN) {
            const float* crow = &cbuf[row * WT_STRIDE + half * 64];
            int cbase = half * 64;
            float elh[2] = {0.f, 0.f}, erh[2] = {0.f, 0.f};
            __half2 hb[32];
#pragma unroll
            for (int j = 0; j < 64; j += 2) {
                float v0 = crow[j], v1 = crow[j + 1];
                int hh = j >> 5;
                elh[hh] += v0 * __ldg(&al[cbase + j]) + v1 * __ldg(&al[cbase + j + 1]);
                erh[hh] += v0 * __ldg(&ar[cbase + j]) + v1 * __ldg(&ar[cbase + j + 1]);
                hb[j >> 1] = __floats2half2_rn(v0, v1);
            }
            uint4* dsth = (uint4*)(g_feat1h + (size_t)grow * 128 + cbase);
            const uint4* srch = (const uint4*)hb;
#pragma unroll
            for (int q = 0; q < 8; q++) dsth[q] = srch[q];
            int hbase = half * 2;
            g_el1[grow * 4 + hbase + 0] = elh[0];
            g_el1[grow * 4 + hbase + 1] = elh[1];
            g_er1[grow * 4 + hbase + 0] = erh[0];
            g_er1[grow * 4 + hbase + 1] = erh[1];
        }
    }
}

// ---------------- K: degree histogram (scalar: max atomic MLP) ---------------
__global__ void hist_kernel(const int* __restrict__ dst) {
    int i = blockIdx.x * blockDim.x + threadIdx.x;
    if (i < EE) atomicAdd(&g_deg[dst[i]], 1);
}

// ---------------- hierarchical scan ------------------------------------------
// K1: per-block sums of g_deg (1024 elems per block)
__global__ __launch_bounds__(SCAN_BLK) void blocksum_kernel() {
    __shared__ int wsum[32];
    int i = blockIdx.x * SCAN_BLK + threadIdx.x;
    int v = (i < NN) ? g_deg[i] : 0;
#pragma unroll
    for (int off = 16; off > 0; off >>= 1) v += __shfl_xor_sync(0xffffffffu, v, off);
    int lane = threadIdx.x & 31, wid = threadIdx.x >> 5;
    if (lane == 0) wsum[wid] = v;
    __syncthreads();
    if (wid == 0) {
        int s = wsum[lane];
#pragma unroll
        for (int off = 16; off > 0; off >>= 1) s += __shfl_xor_sync(0xffffffffu, s, off);
        if (lane == 0) g_blocksum[blockIdx.x] = s;
    }
}

// K2: block-local exclusive scan + (inlined) block offset -> rowptr/pos.
// Self-cleaning: zeroes g_deg after consuming it (invariant for next replay).
__global__ __launch_bounds__(SCAN_BLK) void scan_final_kernel() {
    __shared__ int wsum[32];
    __shared__ int s_boff;
    int t = threadIdx.x;
    int lane = t & 31, wid = t >> 5;

    // block offset: sum of blocksums with index < blockIdx.x (redundant per block)
    {
        int v = (t < NBLK && t < (int)blockIdx.x) ? g_blocksum[t] : 0;
#pragma unroll
        for (int off = 16; off > 0; off >>= 1) v += __shfl_xor_sync(0xffffffffu, v, off);
        if (lane == 0) wsum[wid] = v;
        __syncthreads();
        if (t == 0) {
            int s = 0;
#pragma unroll
            for (int k = 0; k < 32; k++) s += wsum[k];
            s_boff = s;
        }
        __syncthreads();
    }

    int i = blockIdx.x * SCAN_BLK + t;
    int d = (i < NN) ? g_deg[i] : 0;
    int inc = d;
#pragma unroll
    for (int off = 1; off < 32; off <<= 1) {
        int u = __shfl_up_sync(0xffffffffu, inc, off);
        if (lane >= off) inc += u;
    }
    __syncthreads();   // wsum reuse guard (s_boff consumed)
    if (lane == 31) wsum[wid] = inc;
    __syncthreads();
    if (wid == 0) {
        int s = wsum[lane];
        int sinc = s;
#pragma unroll
        for (int off = 1; off < 32; off <<= 1) {
            int u = __shfl_up_sync(0xffffffffu, sinc, off);
            if (lane >= off) sinc += u;
        }
        wsum[lane] = sinc - s;   // exclusive warp prefix
    }
    __syncthreads();
    if (i < NN) {
        int off = s_boff + wsum[wid] + inc - d;
        g_rowptr[i] = off;
        g_pos[i] = off;
        g_deg[i] = 0;            // self-clean for next graph replay
    }
    if (blockIdx.x == 0 && t == 0) g_rowptr[NN] = EE;
}

// ---------------- K: scatter edges into CSR (scalar: max atomic MLP) ---------
__global__ void scatter_kernel(const int* __restrict__ src, const int* __restrict__ dst) {
    int i = blockIdx.x * blockDim.x + threadIdx.x;
    if (i < EE) {
        int p = atomicAdd(&g_pos[dst[i]], 1);
        g_esrc[p] = src[i];
    }
}

// ---------------- K: layer1 aggregation (fused softmax) + mean-head + relu --
// one warp per dst node, 2 edges per iteration (simple loop — the HW
// scoreboard overlaps the gathers; manual pipelining regressed, R11):
//   half = lane>>4 selects edge p+half; sub = lane&15 owns dims 8*sub..8*sub+7
//   head h = sub>>2.
__global__ void agg1_kernel(const float* __restrict__ b1) {
    int w = (blockIdx.x * blockDim.x + threadIdx.x) >> 5;
    if (w >= NN) return;
    int lane = threadIdx.x & 31;
    int half = lane >> 4;
    int sub = lane & 15;
    int h = sub >> 2;
    float ern = g_er1[w * 4 + h];
    float acc[8];
#pragma unroll
    for (int q = 0; q < 8; q++) acc[q] = 0.f;
    float den = 0.f;
    int p0 = g_rowptr[w], p1 = g_rowptr[w + 1];
    for (int p = p0; p < p1; p += 2) {
        int idx = p + half;
        bool valid = idx < p1;
        int s = g_esrc[valid ? idx : p];
        float e = g_el1[s * 4 + h] + ern;
        e = fmaxf(e, 0.2f * e);                       // leaky relu
        float ex = valid ? __expf(e) : 0.f;
        uint4 u = *(const uint4*)(g_feat1h + ((size_t)s << 7) + (sub << 3));
        const __half2* hp = (const __half2*)&u;
#pragma unroll
        for (int q = 0; q < 4; q++) {
            float2 f = __half22float2(hp[q]);
            acc[2 * q]     += ex * f.x;
            acc[2 * q + 1] += ex * f.y;
        }
        den += ex;
    }
    // merge the two edge-halves (same node, disjoint edge subsets)
#pragma unroll
    for (int q = 0; q < 8; q++) acc[q] += __shfl_xor_sync(0xffffffffu, acc[q], 16);
    den += __shfl_xor_sync(0xffffffffu, den, 16);
    float inv = den > 0.f ? 1.f / den : 0.f;
    float v[8];
    float4 b0 = *(const float4*)&b1[sub * 8];
    float4 b1v = *(const float4*)&b1[sub * 8 + 4];
    v[0] = acc[0] * inv + b0.x;  v[1] = acc[1] * inv + b0.y;
    v[2] = acc[2] * inv + b0.z;  v[3] = acc[3] * inv + b0.w;
    v[4] = acc[4] * inv + b1v.x; v[5] = acc[5] * inv + b1v.y;
    v[6] = acc[6] * inv + b1v.z; v[7] = acc[7] * inv + b1v.w;
    // sum over the 4 heads: head = sub>>2 -> xor sub bits 2 (4) and 3 (8)
#pragma unroll
    for (int q = 0; q < 8; q++) {
        v[q] += __shfl_xor_sync(0xffffffffu, v[q], 4);
        v[q] += __shfl_xor_sync(0xffffffffu, v[q], 8);
    }
    if (lane < 4) {   // sub 0..3, half 0: dims d = lane*8 + q
        float4 o0 = make_float4(fmaxf(v[0] * 0.25f, 0.f), fmaxf(v[1] * 0.25f, 0.f),
                                fmaxf(v[2] * 0.25f, 0.f), fmaxf(v[3] * 0.25f, 0.f));
        float4 o1 = make_float4(fmaxf(v[4] * 0.25f, 0.f), fmaxf(v[5] * 0.25f, 0.f),
                                fmaxf(v[6] * 0.25f, 0.f), fmaxf(v[7] * 0.25f, 0.f));
        *(float4*)&g_h2[(size_t)w * 32 + lane * 8] = o0;
        *(float4*)&g_h2[(size_t)w * 32 + lane * 8 + 4] = o1;
    }
}

// ---------------- K: feat2 = h2 @ W2; el2/er2 --------------------------------
__global__ void feat2_kernel(const float* __restrict__ W2,
                             const float* __restrict__ al2,
                             const float* __restrict__ ar2) {
    int n = blockIdx.x * blockDim.x + threadIdx.x;
    if (n >= NN) return;
    float hrow[32];
#pragma unroll
    for (int i = 0; i < 8; i++)
        *(float4*)&hrow[i * 4] = *(const float4*)&g_h2[(size_t)n * 32 + i * 4];
    float out[16];
#pragma unroll
    for (int d = 0; d < 16; d++) out[d] = 0.f;
#pragma unroll
    for (int k = 0; k < 32; k++) {
        float hv = hrow[k];
#pragma unroll
        for (int d = 0; d < 16; d++) out[d] += hv * __ldg(&W2[k * 16 + d]);
    }
    float el = 0.f, er = 0.f;
#pragma unroll
    for (int d = 0; d < 16; d++) {
        el += out[d] * __ldg(&al2[d]);
        er += out[d] * __ldg(&ar2[d]);
    }
#pragma unroll
    for (int i = 0; i < 4; i++)
        *(float4*)&g_feat2[(size_t)n * 16 + i * 4] =
            make_float4(out[i*4+0], out[i*4+1], out[i*4+2], out[i*4+3]);
    g_el2[n] = el;
    g_er2[n] = er;
}

// ---------------- K: layer2 aggregation (fused softmax) ----------------------
__global__ void agg2_kernel(const float* __restrict__ b2, float* __restrict__ out) {
    int g = (blockIdx.x * blockDim.x + threadIdx.x) >> 4;
    if (g >= NN) return;
    int lane = threadIdx.x & 15;
    float ern = g_er2[g];
    float acc = 0.f, den = 0.f;
    int p0 = g_rowptr[g], p1 = g_rowptr[g + 1];
    for (int p = p0; p < p1; p++) {
        int s = g_esrc[p];
        float e = g_el2[s] + ern;
        e = fmaxf(e, 0.2f * e);
        float ex = __expf(e);
        acc += ex * g_feat2[(size_t)s * 16 + lane];
        den += ex;
    }
    float inv = den > 0.f ? 1.f / den : 0.f;
    out[(size_t)g * 16 + lane] = acc * inv + b2[lane];
}

// ---------------- launch ------------------------------------------------------
// Fork/join stream overlap: gemm1 (tensor/smem-bound) on a side stream runs
// concurrently with the CSR build chain (atomic/L2-bound) on the main stream.
extern "C" void kernel_launch(void* const* d_in, const int* in_sizes, int n_in,
                              void* d_out, int out_size) {
    const float* x   = (const float*)d_in[0];
    const int*   src = (const int*)d_in[1];
    const int*   dst = (const int*)d_in[2];
    const float* W1  = (const float*)d_in[3];
    const float* al1 = (const float*)d_in[4];
    const float* ar1 = (const float*)d_in[5];
    const float* b1  = (const float*)d_in[6];
    const float* W2  = (const float*)d_in[7];
    const float* al2 = (const float*)d_in[8];
    const float* ar2 = (const float*)d_in[9];
    const float* b2  = (const float*)d_in[10];
    float* out = (float*)d_out;

    (void)in_sizes; (void)n_in; (void)out_size;

    static cudaStream_t s_side = nullptr;
    static cudaEvent_t s_fork = nullptr, s_join = nullptr;
    if (s_side == nullptr) {
        cudaStreamCreateWithFlags(&s_side, cudaStreamNonBlocking);
        cudaEventCreateWithFlags(&s_fork, cudaEventDisableTiming);
        cudaEventCreateWithFlags(&s_join, cudaEventDisableTiming);
        cudaFuncSetAttribute(gemm1_kernel, cudaFuncAttributeMaxDynamicSharedMemorySize,
                             GEMM_SMEM_BYTES);
    }

    // fork: side stream = gemm1 (independent of the CSR chain)
    cudaEventRecord(s_fork, 0);
    cudaStreamWaitEvent(s_side, s_fork, 0);
    gemm1_kernel<<<(NN + 127) / 128, 256, GEMM_SMEM_BYTES, s_side>>>(x, W1, al1, ar1);
    cudaEventRecord(s_join, s_side);

    // main stream: CSR build chain (g_deg zeroed by previous call's scan_final)
    hist_kernel<<<(EE + 255) / 256, 256>>>(dst);
    blocksum_kernel<<<NBLK, SCAN_BLK>>>();
    scan_final_kernel<<<NBLK, SCAN_BLK>>>();
    scatter_kernel<<<(EE + 255) / 256, 256>>>(src, dst);

    // join: agg1 needs both gemm1 outputs and the CSR
    cudaStreamWaitEvent(0, s_join, 0);
    agg1_kernel<<<(NN * 32 + 255) / 256, 256>>>(b1);
    feat2_kernel<<<(NN + 255) / 256, 256>>>(W2, al2, ar2);
    agg2_kernel<<<(NN * 16 + 255) / 256, 256>>>(b2, out);
}